// round 1
// baseline (speedup 1.0000x reference)
#include <cuda_runtime.h>
#include <cstdint>

#define NS 100
#define NB 64
#define D0 784
#define D1 512
#define D2 512
#define D3 10

// Scratch (device globals: no allocation allowed)
__device__ float g_act0[NS * NB * D1];
__device__ float g_act1[NS * NB * D2];
__device__ float g_sc0[D0 * D1];
__device__ float g_sc1[D1 * D2];
__device__ float g_scl[D2 * D3];
__device__ float g_sb0[D1];
__device__ float g_sb1[D2];
__device__ float g_sbl[D3];

// ---------------------------------------------------------------------------
// Precompute exp(0.5*logvar) scale matrices (shared across all S samples).
// ---------------------------------------------------------------------------
__global__ void precompute_scales(const float* __restrict__ wv0,
                                  const float* __restrict__ wv1,
                                  const float* __restrict__ wvl,
                                  const float* __restrict__ bv0,
                                  const float* __restrict__ bv1,
                                  const float* __restrict__ bvl) {
    int i = blockIdx.x * blockDim.x + threadIdx.x;
    if (i < D0 * D1) g_sc0[i] = expf(0.5f * wv0[i]);
    if (i < D1 * D2) g_sc1[i] = expf(0.5f * wv1[i]);
    if (i < D2 * D3) g_scl[i] = expf(0.5f * wvl[i]);
    if (i < D1) g_sb0[i] = expf(0.5f * bv0[i]);
    if (i < D2) g_sb1[i] = expf(0.5f * bv1[i]);
    if (i < D3) g_sbl[i] = expf(0.5f * bvl[i]);
}

// ---------------------------------------------------------------------------
// Hidden layer: out[s] = relu(A[s] @ (wm + sc .* eps[s]) + bias[s])
// BM=64 (full batch), BN=64, BK=16; 128 threads; 8x4 register tile.
// LAYER==0: A = inputs (broadcast over s), writes g_act0.
// LAYER==1: A = g_act0[s], writes g_act1.
// ---------------------------------------------------------------------------
template <int K, int LAYER>
__global__ __launch_bounds__(128, 4)
void layer_kernel(const float* __restrict__ Ain,
                  const float* __restrict__ eps,
                  const float* __restrict__ wm,
                  const float* __restrict__ bm,
                  const float* __restrict__ be) {
    constexpr int N = 512;
    constexpr int BK = 16;
    const float* sc = (LAYER == 0) ? g_sc0 : g_sc1;
    const float* sb = (LAYER == 0) ? g_sb0 : g_sb1;
    float* out      = (LAYER == 0) ? g_act0 : g_act1;

    __shared__ float As[BK][64];   // A transposed: As[k][m]
    __shared__ float Ws[BK][64];   // W: Ws[k][n]

    const int s   = blockIdx.y;
    const int n0  = blockIdx.x * 64;
    const int tid = threadIdx.x;       // 0..127
    const int tr  = tid >> 4;          // 0..7  (M groups of 8)
    const int tc  = tid & 15;          // 0..15 (N groups of 4)

    const float* A  = (LAYER == 0) ? Ain : (g_act0 + (size_t)s * NB * K);
    const float* E  = eps + (size_t)s * K * N + n0;
    const float* Wm = wm + n0;
    const float* Sc = sc + n0;

    float4 ra[2], re[2], rw[2], rs[2];

    auto load_tile = [&](int k0) {
#pragma unroll
        for (int i = 0; i < 2; ++i) {
            int idx = tid + i * 128;            // 0..255 float4 slots
            int m = idx >> 2, q = idx & 3;      // A tile: 64 rows x 4 quads
            ra[i] = *(const float4*)(A + (size_t)m * K + k0 + q * 4);
            int kr = idx >> 4, nq = idx & 15;   // W tile: 16 rows x 16 quads
            size_t off = (size_t)(k0 + kr) * N + nq * 4;
            re[i] = *(const float4*)(E + off);
            rw[i] = *(const float4*)(Wm + off);
            rs[i] = *(const float4*)(Sc + off);
        }
    };
    auto store_tile = [&]() {
#pragma unroll
        for (int i = 0; i < 2; ++i) {
            int idx = tid + i * 128;
            int m = idx >> 2, q = idx & 3;
            As[q * 4 + 0][m] = ra[i].x;
            As[q * 4 + 1][m] = ra[i].y;
            As[q * 4 + 2][m] = ra[i].z;
            As[q * 4 + 3][m] = ra[i].w;
            int kr = idx >> 4, nq = idx & 15;
            float4 w;
            w.x = fmaf(rs[i].x, re[i].x, rw[i].x);
            w.y = fmaf(rs[i].y, re[i].y, rw[i].y);
            w.z = fmaf(rs[i].z, re[i].z, rw[i].z);
            w.w = fmaf(rs[i].w, re[i].w, rw[i].w);
            *(float4*)&Ws[kr][nq * 4] = w;
        }
    };

    float acc[8][4];
#pragma unroll
    for (int i = 0; i < 8; ++i)
#pragma unroll
        for (int j = 0; j < 4; ++j) acc[i][j] = 0.f;

    load_tile(0);
    constexpr int NT = K / BK;
    for (int t = 0; t < NT; ++t) {
        store_tile();
        __syncthreads();
        if (t + 1 < NT) load_tile((t + 1) * BK);
#pragma unroll
        for (int kk = 0; kk < BK; ++kk) {
            float4 a0 = *(const float4*)&As[kk][tr * 8];
            float4 a1 = *(const float4*)&As[kk][tr * 8 + 4];
            float4 b0 = *(const float4*)&Ws[kk][tc * 4];
            float av[8] = {a0.x, a0.y, a0.z, a0.w, a1.x, a1.y, a1.z, a1.w};
            float bv[4] = {b0.x, b0.y, b0.z, b0.w};
#pragma unroll
            for (int i = 0; i < 8; ++i)
#pragma unroll
                for (int j = 0; j < 4; ++j)
                    acc[i][j] = fmaf(av[i], bv[j], acc[i][j]);
        }
        __syncthreads();
    }

    // Epilogue: bias[s,n] = bm[n] + exp(0.5*bv[n]) * be[s,0,n]; relu; store.
    const float4 bm4 = *(const float4*)(bm + n0 + tc * 4);
    const float4 sb4 = *(const float4*)(sb + n0 + tc * 4);
    const float4 be4 = *(const float4*)(be + (size_t)s * N + n0 + tc * 4);
    float bias[4];
    bias[0] = fmaf(sb4.x, be4.x, bm4.x);
    bias[1] = fmaf(sb4.y, be4.y, bm4.y);
    bias[2] = fmaf(sb4.z, be4.z, bm4.z);
    bias[3] = fmaf(sb4.w, be4.w, bm4.w);

    float* Ob = out + (size_t)s * NB * N + n0;
#pragma unroll
    for (int i = 0; i < 8; ++i) {
        int m = tr * 8 + i;
        float4 o;
        o.x = fmaxf(acc[i][0] + bias[0], 0.f);
        o.y = fmaxf(acc[i][1] + bias[1], 0.f);
        o.z = fmaxf(acc[i][2] + bias[2], 0.f);
        o.w = fmaxf(acc[i][3] + bias[3], 0.f);
        *(float4*)(Ob + (size_t)m * N + tc * 4) = o;
    }
}

// ---------------------------------------------------------------------------
// Last layer (N=10): logits[s] = act1[s] @ (wml + scl .* wel[s]) + bias[s]
// One block per sample. Sampled weight staged in smem as Wsm[o][k]
// (reads k = lane + 32q -> bank = lane, conflict-free).
// ---------------------------------------------------------------------------
__global__ __launch_bounds__(512)
void last_kernel(const float* __restrict__ wel,
                 const float* __restrict__ wml,
                 const float* __restrict__ bml,
                 const float* __restrict__ bel,
                 float* __restrict__ out) {
    __shared__ float Wsm[D3][D2];
    const int s   = blockIdx.x;
    const int tid = threadIdx.x;

    const float* W = wel + (size_t)s * D2 * D3;
    for (int idx = tid; idx < D2 * D3; idx += 512) {
        int k = idx / D3, o = idx % D3;
        Wsm[o][k] = fmaf(g_scl[idx], W[idx], wml[idx]);
    }
    __syncthreads();

    const int w = tid >> 5, lane = tid & 31;  // 16 warps, 4 batch rows each
    const int b0 = w * 4;
    const float* act = g_act1 + (size_t)s * NB * D2;

    float acc[4][D3];
#pragma unroll
    for (int bb = 0; bb < 4; ++bb)
#pragma unroll
        for (int o = 0; o < D3; ++o) acc[bb][o] = 0.f;

    for (int q = 0; q < 16; ++q) {
        int k = q * 32 + lane;
        float wv[D3];
#pragma unroll
        for (int o = 0; o < D3; ++o) wv[o] = Wsm[o][k];
#pragma unroll
        for (int bb = 0; bb < 4; ++bb) {
            float a = act[(size_t)(b0 + bb) * D2 + k];
#pragma unroll
            for (int o = 0; o < D3; ++o)
                acc[bb][o] = fmaf(a, wv[o], acc[bb][o]);
        }
    }

#pragma unroll
    for (int bb = 0; bb < 4; ++bb)
#pragma unroll
        for (int o = 0; o < D3; ++o)
            for (int off = 16; off; off >>= 1)
                acc[bb][o] += __shfl_xor_sync(0xffffffffu, acc[bb][o], off);

    if (lane < D3) {
        float bias = fmaf(g_sbl[lane], bel[s * D3 + lane], bml[lane]);
#pragma unroll
        for (int bb = 0; bb < 4; ++bb) {
            float v = 0.f;
#pragma unroll
            for (int o = 0; o < D3; ++o)
                if (o == lane) v = acc[bb][o];
            out[((size_t)s * NB + b0 + bb) * D3 + lane] = v + bias;
        }
    }
}

// ---------------------------------------------------------------------------
// Input order (metadata): inputs, task_id, wm0, wv0, bm0, bv0, wm1, wv1,
// bm1, bv1, wml, wvl, bml, bvl, we0, be0, we1, be1, wel, bel
// ---------------------------------------------------------------------------
extern "C" void kernel_launch(void* const* d_in, const int* in_sizes, int n_in,
                              void* d_out, int out_size) {
    const float* inputs = (const float*)d_in[0];
    const float* wm0 = (const float*)d_in[2];
    const float* wv0 = (const float*)d_in[3];
    const float* bm0 = (const float*)d_in[4];
    const float* bv0 = (const float*)d_in[5];
    const float* wm1 = (const float*)d_in[6];
    const float* wv1 = (const float*)d_in[7];
    const float* bm1 = (const float*)d_in[8];
    const float* bv1 = (const float*)d_in[9];
    const float* wml = (const float*)d_in[10];
    const float* wvl = (const float*)d_in[11];
    const float* bml = (const float*)d_in[12];
    const float* bvl = (const float*)d_in[13];
    const float* we0 = (const float*)d_in[14];
    const float* be0 = (const float*)d_in[15];
    const float* we1 = (const float*)d_in[16];
    const float* be1 = (const float*)d_in[17];
    const float* wel = (const float*)d_in[18];
    const float* bel = (const float*)d_in[19];
    float* out = (float*)d_out;

    precompute_scales<<<(D0 * D1 + 255) / 256, 256>>>(wv0, wv1, wvl, bv0, bv1, bvl);

    dim3 grid(512 / 64, NS);
    layer_kernel<D0, 0><<<grid, 128>>>(inputs, we0, wm0, bm0, be0);
    layer_kernel<D1, 1><<<grid, 128>>>(inputs, we1, wm1, bm1, be1);

    last_kernel<<<NS, 512>>>(wel, wml, bml, bel, out);
}

// round 2
// speedup vs baseline: 1.6164x; 1.6164x over previous
#include <cuda_runtime.h>
#include <cuda_bf16.h>
#include <cstdint>

#define NS 100
#define NB 64
#define D0 784
#define D1 512
#define D2 512
#define D3 10

// ---------------------------------------------------------------------------
// Device scratch (no allocations allowed)
// ---------------------------------------------------------------------------
__device__ __nv_bfloat16 g_in_h[NB * D0];
__device__ __nv_bfloat16 g_in_l[NB * D0];
__device__ __nv_bfloat16 g_act0_h[NS * NB * D1];
__device__ __nv_bfloat16 g_act0_l[NS * NB * D1];
__device__ __nv_bfloat16 g_act1_h[NS * NB * D2];
__device__ __nv_bfloat16 g_act1_l[NS * NB * D2];
__device__ float g_sc0[D0 * D1];
__device__ float g_sc1[D1 * D2];
__device__ float g_scl[D2 * D3];
__device__ float g_sb0[D1];
__device__ float g_sb1[D2];
__device__ float g_sbl[D3];

__device__ __forceinline__ uint32_t pack_bf2(__nv_bfloat16 a, __nv_bfloat16 b) {
    return (uint32_t)__bfloat16_as_ushort(a) | ((uint32_t)__bfloat16_as_ushort(b) << 16);
}

// ---------------------------------------------------------------------------
// Prep: exp(0.5*logvar) scales + split inputs into bf16 hi/lo planes.
// ---------------------------------------------------------------------------
__global__ void prep_kernel(const float* __restrict__ inputs,
                            const float* __restrict__ wv0,
                            const float* __restrict__ wv1,
                            const float* __restrict__ wvl,
                            const float* __restrict__ bv0,
                            const float* __restrict__ bv1,
                            const float* __restrict__ bvl) {
    int i = blockIdx.x * blockDim.x + threadIdx.x;
    if (i < D0 * D1) g_sc0[i] = expf(0.5f * wv0[i]);
    if (i < D1 * D2) g_sc1[i] = expf(0.5f * wv1[i]);
    if (i < D2 * D3) g_scl[i] = expf(0.5f * wvl[i]);
    if (i < D1) g_sb0[i] = expf(0.5f * bv0[i]);
    if (i < D2) g_sb1[i] = expf(0.5f * bv1[i]);
    if (i < D3) g_sbl[i] = expf(0.5f * bvl[i]);
    if (i < NB * D0) {
        float v = inputs[i];
        __nv_bfloat16 h = __float2bfloat16(v);
        g_in_h[i] = h;
        g_in_l[i] = __float2bfloat16(v - __bfloat162float(h));
    }
}

// ---------------------------------------------------------------------------
// Hidden layer via bf16x3 tensor-core GEMM.
// out[s] = relu(A[s](64xK) @ (wm + sc.*eps[s])(Kx512) + bias[s])
// CTA: 64x64 output tile, BK=32, 128 threads (4 warps, each 32x32).
// A and W split into bf16 hi/lo; acc = Ah*Wh + Ah*Wl + Al*Wh (fp32).
// ---------------------------------------------------------------------------
#define MMA_BF16(C, A, B0, B1)                                                  \
    asm volatile(                                                               \
        "mma.sync.aligned.m16n8k16.row.col.f32.bf16.bf16.f32 "                  \
        "{%0,%1,%2,%3},{%4,%5,%6,%7},{%8,%9},{%0,%1,%2,%3};\n"                  \
        : "+f"((C)[0]), "+f"((C)[1]), "+f"((C)[2]), "+f"((C)[3])                \
        : "r"((A)[0]), "r"((A)[1]), "r"((A)[2]), "r"((A)[3]), "r"(B0), "r"(B1))

#define LDSM_X4(R, ADDR)                                                        \
    asm volatile("ldmatrix.sync.aligned.m8n8.x4.shared.b16 {%0,%1,%2,%3}, [%4];"\
                 : "=r"((R)[0]), "=r"((R)[1]), "=r"((R)[2]), "=r"((R)[3])       \
                 : "r"(ADDR))

#define LDSM_X4_T(R, ADDR)                                                      \
    asm volatile("ldmatrix.sync.aligned.m8n8.x4.trans.shared.b16 "              \
                 "{%0,%1,%2,%3}, [%4];"                                         \
                 : "=r"((R)[0]), "=r"((R)[1]), "=r"((R)[2]), "=r"((R)[3])       \
                 : "r"(ADDR))

template <int K, int LAYER>
__global__ __launch_bounds__(128, 4)
void layer_mma(const float* __restrict__ eps,
               const float* __restrict__ wm,
               const float* __restrict__ bm,
               const float* __restrict__ be) {
    constexpr int N = 512;
    constexpr int BK = 32;
    constexpr int NT = (K + BK - 1) / BK;

    __shared__ __align__(16) __nv_bfloat16 sA[2][64][40];  // [plane][m][k]
    __shared__ __align__(16) __nv_bfloat16 sW[2][32][88];  // [plane][k][n]
    __shared__ float sBias[64];

    const int s = blockIdx.y;
    const int n0 = blockIdx.x * 64;
    const int tid = threadIdx.x;
    const int warp = tid >> 5, lane = tid & 31;
    const int g = lane >> 2, t4 = lane & 3;
    const int wmo = (warp & 1) * 32;   // warp M offset
    const int wno = (warp >> 1) * 32;  // warp N offset

    const float* sc = (LAYER == 0) ? g_sc0 : g_sc1;
    const float* sbv = (LAYER == 0) ? g_sb0 : g_sb1;
    const __nv_bfloat16* Ah_g = (LAYER == 0) ? g_in_h : (g_act0_h + (size_t)s * NB * K);
    const __nv_bfloat16* Al_g = (LAYER == 0) ? g_in_l : (g_act0_l + (size_t)s * NB * K);
    __nv_bfloat16* Oh = ((LAYER == 0) ? g_act0_h : g_act1_h) + (size_t)s * NB * N;
    __nv_bfloat16* Ol = ((LAYER == 0) ? g_act0_l : g_act1_l) + (size_t)s * NB * N;
    const float* E = eps + (size_t)s * K * N;

    if (tid < 64) {
        int n = n0 + tid;
        sBias[tid] = fmaf(sbv[n], be[(size_t)s * N + n], bm[n]);
    }

    float acc[2][4][4];
#pragma unroll
    for (int a = 0; a < 2; ++a)
#pragma unroll
        for (int b = 0; b < 4; ++b)
#pragma unroll
            for (int c = 0; c < 4; ++c) acc[a][b][c] = 0.f;

    // Precompute ldmatrix shared addresses (lane-dependent, k-offset added later)
    const int a_row = (lane & 15);          // + mt*16 + wmo
    const int a_kq = (lane >> 4) * 8;       // col offset within k16
    const int b_krow = (lane & 7) + ((lane >> 3) & 1) * 8;
    const int b_nq = (lane >> 4) * 8;       // + j*16 + wno

    for (int t = 0; t < NT; ++t) {
        const int k0 = t * BK;
        __syncthreads();

        // ---- stage A (both planes), 4 tasks x uint2 (4 bf16) ----
#pragma unroll
        for (int i = 0; i < 4; ++i) {
            int idx = tid + i * 128;          // 512 tasks: 64m x 8 quads
            int m = idx >> 3, q = idx & 7;
            int k = k0 + q * 4;
            uint2 vh = make_uint2(0u, 0u), vl = make_uint2(0u, 0u);
            if (k < K) {
                vh = *(const uint2*)(Ah_g + (size_t)m * K + k);
                vl = *(const uint2*)(Al_g + (size_t)m * K + k);
            }
            *(uint2*)&sA[0][m][q * 4] = vh;
            *(uint2*)&sA[1][m][q * 4] = vl;
        }

        // ---- stage W = wm + sc*eps, split hi/lo, [k][n] layout ----
#pragma unroll
        for (int i = 0; i < 4; ++i) {
            int idx = tid + i * 128;          // 512 tasks: 32k x 16 n-quads
            int kr = idx >> 4, nq = idx & 15;
            int k = k0 + kr;
            float4 w = make_float4(0.f, 0.f, 0.f, 0.f);
            if (k < K) {
                size_t off = (size_t)k * N + n0 + nq * 4;
                float4 e = *(const float4*)(E + off);
                float4 m4 = *(const float4*)(wm + off);
                float4 s4 = *(const float4*)(sc + off);
                w.x = fmaf(s4.x, e.x, m4.x);
                w.y = fmaf(s4.y, e.y, m4.y);
                w.z = fmaf(s4.z, e.z, m4.z);
                w.w = fmaf(s4.w, e.w, m4.w);
            }
            __nv_bfloat16 hx = __float2bfloat16(w.x), hy = __float2bfloat16(w.y);
            __nv_bfloat16 hz = __float2bfloat16(w.z), hw = __float2bfloat16(w.w);
            __nv_bfloat16 lx = __float2bfloat16(w.x - __bfloat162float(hx));
            __nv_bfloat16 ly = __float2bfloat16(w.y - __bfloat162float(hy));
            __nv_bfloat16 lz = __float2bfloat16(w.z - __bfloat162float(hz));
            __nv_bfloat16 lw = __float2bfloat16(w.w - __bfloat162float(hw));
            *(uint2*)&sW[0][kr][nq * 4] = make_uint2(pack_bf2(hx, hy), pack_bf2(hz, hw));
            *(uint2*)&sW[1][kr][nq * 4] = make_uint2(pack_bf2(lx, ly), pack_bf2(lz, lw));
        }
        __syncthreads();

        // ---- 2 x k16 MMA steps ----
#pragma unroll
        for (int kk = 0; kk < BK; kk += 16) {
            uint32_t Afr[2][2][4];  // [plane][mt][reg]
#pragma unroll
            for (int p = 0; p < 2; ++p)
#pragma unroll
                for (int mt = 0; mt < 2; ++mt) {
                    uint32_t addr = (uint32_t)__cvta_generic_to_shared(
                        &sA[p][wmo + mt * 16 + a_row][kk + a_kq]);
                    LDSM_X4(Afr[p][mt], addr);
                }
            uint32_t Bfr[2][2][4];  // [plane][j(n16)][reg]
#pragma unroll
            for (int p = 0; p < 2; ++p)
#pragma unroll
                for (int j = 0; j < 2; ++j) {
                    uint32_t addr = (uint32_t)__cvta_generic_to_shared(
                        &sW[p][kk + b_krow][wno + j * 16 + b_nq]);
                    LDSM_X4_T(Bfr[p][j], addr);
                }
#pragma unroll
            for (int mt = 0; mt < 2; ++mt)
#pragma unroll
                for (int nt = 0; nt < 4; ++nt) {
                    int j = nt >> 1, h = nt & 1;
                    uint32_t b0h = Bfr[0][j][h * 2], b1h = Bfr[0][j][h * 2 + 1];
                    uint32_t b0l = Bfr[1][j][h * 2], b1l = Bfr[1][j][h * 2 + 1];
                    MMA_BF16(acc[mt][nt], Afr[0][mt], b0h, b1h);
                    MMA_BF16(acc[mt][nt], Afr[0][mt], b0l, b1l);
                    MMA_BF16(acc[mt][nt], Afr[1][mt], b0h, b1h);
                }
        }
    }
    __syncthreads();

    // ---- epilogue: bias + relu, split hi/lo, store bf16 pairs ----
#pragma unroll
    for (int mt = 0; mt < 2; ++mt)
#pragma unroll
        for (int nt = 0; nt < 4; ++nt) {
            int r0 = wmo + mt * 16 + g, r1 = r0 + 8;
            int c0 = wno + nt * 8 + t4 * 2;
            float bia0 = sBias[c0], bia1 = sBias[c0 + 1];
            float v00 = fmaxf(acc[mt][nt][0] + bia0, 0.f);
            float v01 = fmaxf(acc[mt][nt][1] + bia1, 0.f);
            float v10 = fmaxf(acc[mt][nt][2] + bia0, 0.f);
            float v11 = fmaxf(acc[mt][nt][3] + bia1, 0.f);
            __nv_bfloat16 h00 = __float2bfloat16(v00), h01 = __float2bfloat16(v01);
            __nv_bfloat16 h10 = __float2bfloat16(v10), h11 = __float2bfloat16(v11);
            __nv_bfloat16 l00 = __float2bfloat16(v00 - __bfloat162float(h00));
            __nv_bfloat16 l01 = __float2bfloat16(v01 - __bfloat162float(h01));
            __nv_bfloat16 l10 = __float2bfloat16(v10 - __bfloat162float(h10));
            __nv_bfloat16 l11 = __float2bfloat16(v11 - __bfloat162float(h11));
            size_t o0 = (size_t)r0 * N + n0 + c0;
            size_t o1 = (size_t)r1 * N + n0 + c0;
            *(uint32_t*)(Oh + o0) = pack_bf2(h00, h01);
            *(uint32_t*)(Ol + o0) = pack_bf2(l00, l01);
            *(uint32_t*)(Oh + o1) = pack_bf2(h10, h11);
            *(uint32_t*)(Ol + o1) = pack_bf2(l10, l11);
        }
}

// ---------------------------------------------------------------------------
// Last layer (N=10): grid (100 s, 4 row-groups), 128 threads.
// ---------------------------------------------------------------------------
__global__ __launch_bounds__(128)
void last_kernel(const float* __restrict__ wel,
                 const float* __restrict__ wml,
                 const float* __restrict__ bml,
                 const float* __restrict__ bel,
                 float* __restrict__ out) {
    __shared__ float Wsm[D3][D2];
    const int s = blockIdx.x, rg = blockIdx.y;
    const int tid = threadIdx.x;

    const float* W = wel + (size_t)s * D2 * D3;
    for (int idx = tid; idx < D2 * D3; idx += 128) {
        int k = idx / D3, o = idx % D3;
        Wsm[o][k] = fmaf(g_scl[idx], W[idx], wml[idx]);
    }
    __syncthreads();

    const int w = tid >> 5, lane = tid & 31;
    const int r0 = rg * 16 + w * 4;
    const __nv_bfloat16* Ah = g_act1_h + (size_t)s * NB * D2;
    const __nv_bfloat16* Al = g_act1_l + (size_t)s * NB * D2;

    float acc[4][D3];
#pragma unroll
    for (int bb = 0; bb < 4; ++bb)
#pragma unroll
        for (int o = 0; o < D3; ++o) acc[bb][o] = 0.f;

    for (int q = 0; q < 16; ++q) {
        int k = q * 32 + lane;
        float wv[D3];
#pragma unroll
        for (int o = 0; o < D3; ++o) wv[o] = Wsm[o][k];
#pragma unroll
        for (int bb = 0; bb < 4; ++bb) {
            size_t off = (size_t)(r0 + bb) * D2 + k;
            float a = __bfloat162float(Ah[off]) + __bfloat162float(Al[off]);
#pragma unroll
            for (int o = 0; o < D3; ++o)
                acc[bb][o] = fmaf(a, wv[o], acc[bb][o]);
        }
    }

#pragma unroll
    for (int bb = 0; bb < 4; ++bb)
#pragma unroll
        for (int o = 0; o < D3; ++o)
            for (int off = 16; off; off >>= 1)
                acc[bb][o] += __shfl_xor_sync(0xffffffffu, acc[bb][o], off);

    if (lane < D3) {
        float bias = fmaf(g_sbl[lane], bel[s * D3 + lane], bml[lane]);
#pragma unroll
        for (int bb = 0; bb < 4; ++bb) {
            float v = 0.f;
#pragma unroll
            for (int o = 0; o < D3; ++o)
                if (o == lane) v = acc[bb][o];
            out[((size_t)s * NB + r0 + bb) * D3 + lane] = v + bias;
        }
    }
}

// ---------------------------------------------------------------------------
// metadata order: inputs, task_id, wm0, wv0, bm0, bv0, wm1, wv1, bm1, bv1,
// wml, wvl, bml, bvl, we0, be0, we1, be1, wel, bel
// ---------------------------------------------------------------------------
extern "C" void kernel_launch(void* const* d_in, const int* in_sizes, int n_in,
                              void* d_out, int out_size) {
    const float* inputs = (const float*)d_in[0];
    const float* wm0 = (const float*)d_in[2];
    const float* wv0 = (const float*)d_in[3];
    const float* bm0 = (const float*)d_in[4];
    const float* bv0 = (const float*)d_in[5];
    const float* wm1 = (const float*)d_in[6];
    const float* wv1 = (const float*)d_in[7];
    const float* bm1 = (const float*)d_in[8];
    const float* bv1 = (const float*)d_in[9];
    const float* wml = (const float*)d_in[10];
    const float* wvl = (const float*)d_in[11];
    const float* bml = (const float*)d_in[12];
    const float* bvl = (const float*)d_in[13];
    const float* we0 = (const float*)d_in[14];
    const float* be0 = (const float*)d_in[15];
    const float* we1 = (const float*)d_in[16];
    const float* be1 = (const float*)d_in[17];
    const float* wel = (const float*)d_in[18];
    const float* bel = (const float*)d_in[19];
    float* out = (float*)d_out;

    prep_kernel<<<(D0 * D1 + 255) / 256, 256>>>(inputs, wv0, wv1, wvl, bv0, bv1, bvl);

    dim3 grid(8, NS);
    layer_mma<D0, 0><<<grid, 128>>>(we0, wm0, bm0, be0);
    layer_mma<D1, 1><<<grid, 128>>>(we1, wm1, bm1, be1);

    last_kernel<<<dim3(NS, 4), 128>>>(wel, wml, bml, bel, out);
}

// round 3
// speedup vs baseline: 1.8413x; 1.1391x over previous
#include <cuda_runtime.h>
#include <cuda_fp16.h>
#include <cstdint>

#define NS 100
#define NB 64
#define D0 784
#define D1 512
#define D2 512
#define D3 10

// ---------------------------------------------------------------------------
// Device scratch (no allocations allowed)
// ---------------------------------------------------------------------------
__device__ __half g_in_h[NB * D0];
__device__ __half g_in_l[NB * D0];
__device__ __half g_act0_h[NS * NB * D1];
__device__ __half g_act0_l[NS * NB * D1];
__device__ __half g_act1_h[NS * NB * D2];
__device__ __half g_act1_l[NS * NB * D2];
__device__ float g_sc0[D0 * D1];
__device__ float g_sc1[D1 * D2];
__device__ float g_scl[D2 * D3];
__device__ float g_sb0[D1];
__device__ float g_sb1[D2];
__device__ float g_sbl[D3];

__device__ __forceinline__ uint32_t pack_h2(__half a, __half b) {
    __half2 h2 = __halves2half2(a, b);
    return *(uint32_t*)&h2;
}

// ---------------------------------------------------------------------------
// Prep: exp(0.5*logvar) scales + split inputs into fp16 hi/lo planes.
// ---------------------------------------------------------------------------
__global__ void prep_kernel(const float* __restrict__ inputs,
                            const float* __restrict__ wv0,
                            const float* __restrict__ wv1,
                            const float* __restrict__ wvl,
                            const float* __restrict__ bv0,
                            const float* __restrict__ bv1,
                            const float* __restrict__ bvl) {
    int i = blockIdx.x * blockDim.x + threadIdx.x;
    if (i < D0 * D1) g_sc0[i] = expf(0.5f * wv0[i]);
    if (i < D1 * D2) g_sc1[i] = expf(0.5f * wv1[i]);
    if (i < D2 * D3) g_scl[i] = expf(0.5f * wvl[i]);
    if (i < D1) g_sb0[i] = expf(0.5f * bv0[i]);
    if (i < D2) g_sb1[i] = expf(0.5f * bv1[i]);
    if (i < D3) g_sbl[i] = expf(0.5f * bvl[i]);
    if (i < NB * D0) {
        float v = inputs[i];
        __half h = __float2half_rn(v);
        g_in_h[i] = h;
        g_in_l[i] = __float2half_rn(v - __half2float(h));
    }
}

// ---------------------------------------------------------------------------
// Hidden layer: out[s] = relu(A[s](64xK) @ (wm + sc.*eps[s])(Kx512) + bias)
// fp16 tensor cores: A split hi/lo (2 planes), W single plane (fp16-rounded).
// CTA 64x64 tile, BK=16, 128 threads (4 warps, 32x32 each).
// Register-prefetch + double-buffered smem, 1 sync per k-tile.
// ---------------------------------------------------------------------------
#define MMA_F16(C, A, B0, B1)                                                   \
    asm volatile(                                                               \
        "mma.sync.aligned.m16n8k16.row.col.f32.f16.f16.f32 "                    \
        "{%0,%1,%2,%3},{%4,%5,%6,%7},{%8,%9},{%0,%1,%2,%3};\n"                  \
        : "+f"((C)[0]), "+f"((C)[1]), "+f"((C)[2]), "+f"((C)[3])                \
        : "r"((A)[0]), "r"((A)[1]), "r"((A)[2]), "r"((A)[3]), "r"(B0), "r"(B1))

#define LDSM_X4(R, ADDR)                                                        \
    asm volatile("ldmatrix.sync.aligned.m8n8.x4.shared.b16 {%0,%1,%2,%3}, [%4];"\
                 : "=r"((R)[0]), "=r"((R)[1]), "=r"((R)[2]), "=r"((R)[3])       \
                 : "r"(ADDR))

#define LDSM_X4_T(R, ADDR)                                                      \
    asm volatile("ldmatrix.sync.aligned.m8n8.x4.trans.shared.b16 "              \
                 "{%0,%1,%2,%3}, [%4];"                                         \
                 : "=r"((R)[0]), "=r"((R)[1]), "=r"((R)[2]), "=r"((R)[3])       \
                 : "r"(ADDR))

template <int K, int LAYER>
__global__ __launch_bounds__(128, 4)
void layer_mma(const float* __restrict__ eps,
               const float* __restrict__ wm,
               const float* __restrict__ bm,
               const float* __restrict__ be) {
    constexpr int N = 512;
    constexpr int BK = 16;
    constexpr int NT = K / BK;   // 49 or 32, exact

    __shared__ __align__(16) __half sA[2][2][64][24];  // [buf][plane][m][k]
    __shared__ __align__(16) __half sW[2][16][72];     // [buf][k][n]
    __shared__ float sBias[64];

    const int s = blockIdx.y;
    const int n0 = blockIdx.x * 64;
    const int tid = threadIdx.x;
    const int warp = tid >> 5, lane = tid & 31;
    const int g = lane >> 2, t4 = lane & 3;
    const int wmo = (warp & 1) * 32;   // warp M offset
    const int wno = (warp >> 1) * 32;  // warp N offset

    const float* sc = (LAYER == 0) ? g_sc0 : g_sc1;
    const float* sbv = (LAYER == 0) ? g_sb0 : g_sb1;
    const __half* Ah_g = (LAYER == 0) ? g_in_h : (g_act0_h + (size_t)s * NB * K);
    const __half* Al_g = (LAYER == 0) ? g_in_l : (g_act0_l + (size_t)s * NB * K);
    __half* Oh = ((LAYER == 0) ? g_act0_h : g_act1_h) + (size_t)s * NB * N;
    __half* Ol = ((LAYER == 0) ? g_act0_l : g_act1_l) + (size_t)s * NB * N;
    const float* E = eps + (size_t)s * K * N;

    if (tid < 64) {
        int n = n0 + tid;
        sBias[tid] = fmaf(sbv[n], be[(size_t)s * N + n], bm[n]);
    }

    // Staging thread mapping
    const int a_m = tid >> 1, a_ko = (tid & 1) * 8;   // A: 64 rows x 2 uint4
    const int w_kr = tid >> 3, w_nb = (tid & 7) * 8;  // W: 16 rows x 8 cols/thr

    // Prefetch registers
    uint4 ra0, ra1;
    float4 re0, re1, rw0, rw1, rs0, rs1;

    auto ldg = [&](int t) {
        const int k0 = t * BK;
        ra0 = *(const uint4*)(Ah_g + (size_t)a_m * K + k0 + a_ko);
        ra1 = *(const uint4*)(Al_g + (size_t)a_m * K + k0 + a_ko);
        size_t off = (size_t)(k0 + w_kr) * N + n0 + w_nb;
        re0 = *(const float4*)(E + off);
        re1 = *(const float4*)(E + off + 4);
        rw0 = *(const float4*)(wm + off);
        rw1 = *(const float4*)(wm + off + 4);
        rs0 = *(const float4*)(sc + off);
        rs1 = *(const float4*)(sc + off + 4);
    };

    auto sts = [&](int b) {
        *(uint4*)&sA[b][0][a_m][a_ko] = ra0;
        *(uint4*)&sA[b][1][a_m][a_ko] = ra1;
        float w[8];
        w[0] = fmaf(rs0.x, re0.x, rw0.x);
        w[1] = fmaf(rs0.y, re0.y, rw0.y);
        w[2] = fmaf(rs0.z, re0.z, rw0.z);
        w[3] = fmaf(rs0.w, re0.w, rw0.w);
        w[4] = fmaf(rs1.x, re1.x, rw1.x);
        w[5] = fmaf(rs1.y, re1.y, rw1.y);
        w[6] = fmaf(rs1.z, re1.z, rw1.z);
        w[7] = fmaf(rs1.w, re1.w, rw1.w);
        uint4 p;
        p.x = pack_h2(__float2half_rn(w[0]), __float2half_rn(w[1]));
        p.y = pack_h2(__float2half_rn(w[2]), __float2half_rn(w[3]));
        p.z = pack_h2(__float2half_rn(w[4]), __float2half_rn(w[5]));
        p.w = pack_h2(__float2half_rn(w[6]), __float2half_rn(w[7]));
        *(uint4*)&sW[b][w_kr][w_nb] = p;
    };

    float acc[2][4][4];
#pragma unroll
    for (int a = 0; a < 2; ++a)
#pragma unroll
        for (int b = 0; b < 4; ++b)
#pragma unroll
            for (int c = 0; c < 4; ++c) acc[a][b][c] = 0.f;

    // ldmatrix lane addressing (same pattern as validated R2 kernel)
    const int a_row = lane & 15;
    const int a_kq = (lane >> 4) * 8;
    const int b_krow = (lane & 7) + ((lane >> 3) & 1) * 8;
    const int b_nq = (lane >> 4) * 8;

    ldg(0);
    for (int t = 0; t < NT; ++t) {
        const int b = t & 1;
        sts(b);
        __syncthreads();
        if (t + 1 < NT) ldg(t + 1);

        uint32_t Afr[2][2][4];
#pragma unroll
        for (int p = 0; p < 2; ++p)
#pragma unroll
            for (int mt = 0; mt < 2; ++mt) {
                uint32_t addr = (uint32_t)__cvta_generic_to_shared(
                    &sA[b][p][wmo + mt * 16 + a_row][a_kq]);
                LDSM_X4(Afr[p][mt], addr);
            }
        uint32_t Bfr[2][4];
#pragma unroll
        for (int j = 0; j < 2; ++j) {
            uint32_t addr = (uint32_t)__cvta_generic_to_shared(
                &sW[b][b_krow][wno + j * 16 + b_nq]);
            LDSM_X4_T(Bfr[j], addr);
        }
#pragma unroll
        for (int mt = 0; mt < 2; ++mt)
#pragma unroll
            for (int nt = 0; nt < 4; ++nt) {
                int j = nt >> 1, h = nt & 1;
                uint32_t b0 = Bfr[j][h * 2], b1 = Bfr[j][h * 2 + 1];
                MMA_F16(acc[mt][nt], Afr[0][mt], b0, b1);
                MMA_F16(acc[mt][nt], Afr[1][mt], b0, b1);
            }
    }

    // ---- epilogue: bias + relu, split hi/lo fp16, store pairs ----
#pragma unroll
    for (int mt = 0; mt < 2; ++mt)
#pragma unroll
        for (int nt = 0; nt < 4; ++nt) {
            int r0 = wmo + mt * 16 + g, r1 = r0 + 8;
            int c0 = wno + nt * 8 + t4 * 2;
            float bia0 = sBias[c0], bia1 = sBias[c0 + 1];
            float v00 = fmaxf(acc[mt][nt][0] + bia0, 0.f);
            float v01 = fmaxf(acc[mt][nt][1] + bia1, 0.f);
            float v10 = fmaxf(acc[mt][nt][2] + bia0, 0.f);
            float v11 = fmaxf(acc[mt][nt][3] + bia1, 0.f);
            __half h00 = __float2half_rn(v00), h01 = __float2half_rn(v01);
            __half h10 = __float2half_rn(v10), h11 = __float2half_rn(v11);
            __half l00 = __float2half_rn(v00 - __half2float(h00));
            __half l01 = __float2half_rn(v01 - __half2float(h01));
            __half l10 = __float2half_rn(v10 - __half2float(h10));
            __half l11 = __float2half_rn(v11 - __half2float(h11));
            size_t o0 = (size_t)r0 * N + n0 + c0;
            size_t o1 = (size_t)r1 * N + n0 + c0;
            *(uint32_t*)(Oh + o0) = pack_h2(h00, h01);
            *(uint32_t*)(Ol + o0) = pack_h2(l00, l01);
            *(uint32_t*)(Oh + o1) = pack_h2(h10, h11);
            *(uint32_t*)(Ol + o1) = pack_h2(l10, l11);
        }
}

// ---------------------------------------------------------------------------
// Last layer (N=10), fp32: grid (100 s, 4 row-groups) x 256 threads.
// Each block: stage sampled W (10x512) in smem, 8 warps x 2 batch rows.
// ---------------------------------------------------------------------------
__global__ __launch_bounds__(256)
void last_kernel(const float* __restrict__ wel,
                 const float* __restrict__ wml,
                 const float* __restrict__ bml,
                 const float* __restrict__ bel,
                 float* __restrict__ out) {
    __shared__ float Wsm[D3][D2];
    const int s = blockIdx.x, rg = blockIdx.y;
    const int tid = threadIdx.x;

    const float* W = wel + (size_t)s * D2 * D3;
    for (int idx = tid; idx < D2 * D3; idx += 256) {
        int k = idx / D3, o = idx - k * D3;
        Wsm[o][k] = fmaf(g_scl[idx], W[idx], wml[idx]);
    }
    __syncthreads();

    const int w = tid >> 5, lane = tid & 31;
    const int r0 = rg * 16 + w * 2;   // 2 rows per warp
    const __half* Ah = g_act1_h + (size_t)s * NB * D2;
    const __half* Al = g_act1_l + (size_t)s * NB * D2;

    float acc[2][D3];
#pragma unroll
    for (int bb = 0; bb < 2; ++bb)
#pragma unroll
        for (int o = 0; o < D3; ++o) acc[bb][o] = 0.f;

    for (int q = 0; q < 16; ++q) {
        int k = q * 32 + lane;
        float wv[D3];
#pragma unroll
        for (int o = 0; o < D3; ++o) wv[o] = Wsm[o][k];
#pragma unroll
        for (int bb = 0; bb < 2; ++bb) {
            size_t off = (size_t)(r0 + bb) * D2 + k;
            float a = __half2float(Ah[off]) + __half2float(Al[off]);
#pragma unroll
            for (int o = 0; o < D3; ++o)
                acc[bb][o] = fmaf(a, wv[o], acc[bb][o]);
        }
    }

#pragma unroll
    for (int bb = 0; bb < 2; ++bb)
#pragma unroll
        for (int o = 0; o < D3; ++o)
            for (int off = 16; off; off >>= 1)
                acc[bb][o] += __shfl_xor_sync(0xffffffffu, acc[bb][o], off);

    if (lane < D3) {
        float bias = fmaf(g_sbl[lane], bel[s * D3 + lane], bml[lane]);
#pragma unroll
        for (int bb = 0; bb < 2; ++bb) {
            float v = 0.f;
#pragma unroll
            for (int o = 0; o < D3; ++o)
                if (o == lane) v = acc[bb][o];
            out[((size_t)s * NB + r0 + bb) * D3 + lane] = v + bias;
        }
    }
}

// ---------------------------------------------------------------------------
// metadata order: inputs, task_id, wm0, wv0, bm0, bv0, wm1, wv1, bm1, bv1,
// wml, wvl, bml, bvl, we0, be0, we1, be1, wel, bel
// ---------------------------------------------------------------------------
extern "C" void kernel_launch(void* const* d_in, const int* in_sizes, int n_in,
                              void* d_out, int out_size) {
    const float* inputs = (const float*)d_in[0];
    const float* wm0 = (const float*)d_in[2];
    const float* wv0 = (const float*)d_in[3];
    const float* bm0 = (const float*)d_in[4];
    const float* bv0 = (const float*)d_in[5];
    const float* wm1 = (const float*)d_in[6];
    const float* wv1 = (const float*)d_in[7];
    const float* bm1 = (const float*)d_in[8];
    const float* bv1 = (const float*)d_in[9];
    const float* wml = (const float*)d_in[10];
    const float* wvl = (const float*)d_in[11];
    const float* bml = (const float*)d_in[12];
    const float* bvl = (const float*)d_in[13];
    const float* we0 = (const float*)d_in[14];
    const float* be0 = (const float*)d_in[15];
    const float* we1 = (const float*)d_in[16];
    const float* be1 = (const float*)d_in[17];
    const float* wel = (const float*)d_in[18];
    const float* bel = (const float*)d_in[19];
    float* out = (float*)d_out;

    prep_kernel<<<(D0 * D1 + 255) / 256, 256>>>(inputs, wv0, wv1, wvl, bv0, bv1, bvl);

    dim3 grid(8, NS);
    layer_mma<D0, 0><<<grid, 128>>>(we0, wm0, bm0, be0);
    layer_mma<D1, 1><<<grid, 128>>>(we1, wm1, bm1, be1);

    last_kernel<<<dim3(NS, 4), 256>>>(wel, wml, bml, bel, out);
}